// round 14
// baseline (speedup 1.0000x reference)
#include <cuda_runtime.h>
#include <cuda_fp16.h>
#include <cstdint>
#include <math.h>

#define B_ 8
#define C_ 128
#define N_ 2048
#define K2C 256
#define KSPLIT 16
#define SLOPE 0.2f

typedef unsigned int u32;
typedef __half f16;

// ---------------- device scratch (allocation-free) ----------------
__device__ float g_epart[KSPLIT * B_ * C_ * C_];            // energy partials
__device__ f16 g_xcH[B_ * K2C * N_];                        // xc = [x_glb; x] hi
__device__ f16 g_xL[B_ * C_ * N_];                          // x lo (energy only)
__device__ f16 g_wadjH[N_ * K2C];
__device__ f16 g_wdynH[C_ * C_];
__device__ f16 g_attH[B_ * C_ * C_];
__device__ f16 g_adjH[(size_t)B_ * N_ * N_];

// ---------------- primitives ----------------
__device__ __forceinline__ u32 smem_u32(const void* p) {
    u32 a;
    asm("{ .reg .u64 t; cvta.to.shared.u64 t, %1; cvt.u32.u64 %0, t; }"
        : "=r"(a) : "l"(p));
    return a;
}
__device__ __forceinline__ void ldsm4(u32* r, u32 addr) {
    asm volatile("ldmatrix.sync.aligned.m8n8.x4.shared.b16 {%0,%1,%2,%3}, [%4];"
                 : "=r"(r[0]), "=r"(r[1]), "=r"(r[2]), "=r"(r[3]) : "r"(addr));
}
__device__ __forceinline__ void ldsm4t(u32* r, u32 addr) {
    asm volatile("ldmatrix.sync.aligned.m8n8.x4.trans.shared.b16 {%0,%1,%2,%3}, [%4];"
                 : "=r"(r[0]), "=r"(r[1]), "=r"(r[2]), "=r"(r[3]) : "r"(addr));
}
__device__ __forceinline__ void mma_f16(float* c, const u32* a, const u32* b) {
    asm volatile(
        "mma.sync.aligned.m16n8k16.row.col.f32.f16.f16.f32 "
        "{%0,%1,%2,%3}, {%4,%5,%6,%7}, {%8,%9}, {%0,%1,%2,%3};"
        : "+f"(c[0]), "+f"(c[1]), "+f"(c[2]), "+f"(c[3])
        : "r"(a[0]), "r"(a[1]), "r"(a[2]), "r"(a[3]), "r"(b[0]), "r"(b[1]));
}
__device__ __forceinline__ void cpa16(u32 dst, const void* src) {
    asm volatile("cp.async.cg.shared.global [%0], [%1], 16;" :: "r"(dst), "l"(src));
}
#define CP_COMMIT() asm volatile("cp.async.commit_group;" ::: "memory")
#define CP_WAIT1() asm volatile("cp.async.wait_group 1;" ::: "memory")
#define CP_WAIT0() asm volatile("cp.async.wait_group 0;" ::: "memory")

#define SWZ(o) ((o) ^ (((o) >> 3) & 0x70))

// default (R11) layout: A and B double-buffered, 2 x 32KB = 64KB
#define SM_A(b) ((b) * 32768)
#define SM_B(b) ((b) * 32768 + 16384)
#define SMEM_SZ 65536
#define SMEM_SZ_BIG 98304    // fused y1y2
#define SMEM_SZ_ADJ 131072   // adj: A resident 64KB + B 2x32KB

__device__ __forceinline__ void split1(float v, f16& h, f16& l) {
    h = __float2half_rn(v);
    l = __float2half_rn(v - __half2float(h));
}
__device__ __forceinline__ u32 packh2(f16 a, f16 b) {
    return (u32)__half_as_ushort(a) | ((u32)__half_as_ushort(b) << 16);
}
__device__ __forceinline__ float leaky(float v) { return v > 0.0f ? v : SLOPE * v; }
__device__ __forceinline__ float sigm(float v) { return 1.0f / (1.0f + __expf(-v)); }

// ---------------- staging (256 threads) ----------------
__device__ __forceinline__ void stA(u32 sbase, const f16* __restrict__ src,
                                    int lda, int tid) {
    int row = tid & 127, g = tid >> 7;
    const f16* p = src + (size_t)row * lda + g * 32;
#pragma unroll
    for (int i = 0; i < 4; ++i) {
        int ch = g * 4 + i;
        cpa16(sbase + (u32)SWZ(row * 128 + ch * 16), p + i * 8);
    }
}
__device__ __forceinline__ void stB(u32 sbase, const f16* __restrict__ src,
                                    int ldb, int tid) {
    int kr = tid >> 2, q = tid & 3;
    const f16* p = src + (size_t)kr * ldb + q * 32;
#pragma unroll
    for (int i = 0; i < 4; ++i) {
        int ch = q * 4 + i;
        cpa16(sbase + (u32)(kr * 256 + ((ch ^ (kr & 15)) & 15) * 16), p + i * 8);
    }
}

// ---- single-pass chunk (A f16, B f16 via trans). Warp tile 32x64. ----
__device__ __forceinline__ void chunk_sp(u32 sA, u32 sB, int wm, int wn,
                                         int lane, float acc[2][8][4]) {
#pragma unroll
    for (int s = 0; s < 4; ++s) {
        int k0 = s * 16;
        u32 ah[2][4];
        {
            int am = lane & 15, ak = k0 + (lane >> 4) * 8;
            ldsm4(ah[0], sA + (u32)SWZ((wm + am) * 128 + ak * 2));
            ldsm4(ah[1], sA + (u32)SWZ((wm + 16 + am) * 128 + ak * 2));
        }
#pragma unroll
        for (int g = 0; g < 4; ++g) {
            u32 bh[4];
            int t = lane >> 3, r = lane & 7;
            int k = k0 + (t & 1) * 8 + r;
            int nc = ((wn + g * 16) >> 3) + (t >> 1);
            ldsm4t(bh, sB + (u32)(k * 256 + ((nc ^ (k & 15)) & 15) * 16));
#pragma unroll
            for (int mf = 0; mf < 2; ++mf)
#pragma unroll
                for (int nf = 0; nf < 2; ++nf)
                    mma_f16(acc[mf][g * 2 + nf], ah[mf], bh + nf * 2);
        }
    }
}

// ---- wide chunk: warp tile 64x64 (adj, 1 CTA/SM, 256 regs) ----
__device__ __forceinline__ void chunk64(u32 sA, u32 sB, int wm, int wn,
                                        int lane, float acc[4][8][4]) {
#pragma unroll
    for (int s = 0; s < 4; ++s) {
        int k0 = s * 16;
        u32 ah[4][4];
        int am = lane & 15, ak = k0 + (lane >> 4) * 8;
#pragma unroll
        for (int mf = 0; mf < 4; ++mf)
            ldsm4(ah[mf], sA + (u32)SWZ((wm + mf * 16 + am) * 128 + ak * 2));
#pragma unroll
        for (int g = 0; g < 4; ++g) {
            u32 bh[4];
            int t = lane >> 3;
            int k = k0 + (t & 1) * 8 + (lane & 7);
            int nc = ((wn + g * 16) >> 3) + (t >> 1);
            ldsm4t(bh, sB + (u32)(k * 256 + ((nc ^ (k & 15)) & 15) * 16));
#pragma unroll
            for (int mf = 0; mf < 4; ++mf)
#pragma unroll
                for (int nf = 0; nf < 2; ++nf)
                    mma_f16(acc[mf][g * 2 + nf], ah[mf], bh + nf * 2);
        }
    }
}

// ---- energy chunk: 3-pass both-split, B frags from the A tiles ----
__device__ __forceinline__ void chunk_sym(u32 sAH, u32 sAL, int wm, int wn,
                                          int lane, float acc[2][8][4]) {
#pragma unroll
    for (int s = 0; s < 4; ++s) {
        int k0 = s * 16;
        u32 ah[2][4], al[2][4];
        {
            int am = lane & 15, ak = k0 + (lane >> 4) * 8;
            u32 o0 = (u32)SWZ((wm + am) * 128 + ak * 2);
            u32 o1 = (u32)SWZ((wm + 16 + am) * 128 + ak * 2);
            ldsm4(ah[0], sAH + o0);
            ldsm4(ah[1], sAH + o1);
            ldsm4(al[0], sAL + o0);
            ldsm4(al[1], sAL + o1);
        }
#pragma unroll
        for (int g = 0; g < 4; ++g) {
            u32 bh[4], bl[4];
            int t = lane >> 3, r = lane & 7;
            int n = wn + g * 16 + (t >> 1) * 8 + r;
            int k = k0 + (t & 1) * 8;
            u32 boff = (u32)SWZ(n * 128 + k * 2);
            ldsm4(bh, sAH + boff);
            ldsm4(bl, sAL + boff);
#pragma unroll
            for (int mf = 0; mf < 2; ++mf)
#pragma unroll
                for (int nf = 0; nf < 2; ++nf) {
                    float* c = acc[mf][g * 2 + nf];
                    mma_f16(c, ah[mf], bh + nf * 2);
                    mma_f16(c, ah[mf], bl + nf * 2);
                    mma_f16(c, al[mf], bh + nf * 2);
                }
        }
    }
}

// R11 double-buffered mainloop (A + B one chunk ahead).
__device__ __forceinline__ void gemm_sp(u32 sb, const f16* aH, int lda,
                                        const f16* bH, int ldb, int nc_total,
                                        int tid, int wm, int wn, int lane,
                                        float acc[2][8][4]) {
    stA(sb + SM_A(0), aH, lda, tid);
    stB(sb + SM_B(0), bH, ldb, tid);
    CP_COMMIT();
    if (nc_total > 1) {
        stA(sb + SM_A(1), aH + 64, lda, tid);
        stB(sb + SM_B(1), bH + (size_t)64 * ldb, ldb, tid);
        CP_COMMIT();
    }
#pragma unroll 1
    for (int kc = 0; kc < nc_total; ++kc) {
        if (kc + 1 < nc_total) CP_WAIT1(); else CP_WAIT0();
        __syncthreads();
        int cb = kc & 1;
        chunk_sp(sb + SM_A(cb), sb + SM_B(cb), wm, wn, lane, acc);
        __syncthreads();
        if (kc + 2 < nc_total) {
            stA(sb + SM_A(cb), aH + (size_t)(kc + 2) * 64, lda, tid);
            stB(sb + SM_B(cb), bH + (size_t)(kc + 2) * 64 * ldb, ldb, tid);
            CP_COMMIT();
        }
    }
}

// ---------------- pre-pass: convert weights + x to f16 -----------------------
__global__ void k_cvt(const float* __restrict__ w_adj,
                      const float* __restrict__ w_dyn,
                      const float* __restrict__ x) {
    int i0 = blockIdx.x * blockDim.x + threadIdx.x;
    int st = gridDim.x * blockDim.x;
    for (int i = i0; i < N_ * K2C; i += st)
        g_wadjH[i] = __float2half_rn(w_adj[i]);
    for (int i = i0; i < C_ * C_; i += st)
        g_wdynH[i] = __float2half_rn(w_dyn[i]);
    for (int i = i0; i < B_ * C_ * N_; i += st) {
        int b = i / (C_ * N_);
        int rem = i - b * C_ * N_;
        f16 h, l;
        split1(x[i], h, l);
        g_xcH[(size_t)b * K2C * N_ + 128 * N_ + rem] = h;  // xc rows 128..255 = x
        g_xL[i] = l;                                       // lo kept for energy
    }
}

// ---------------- energy partials (3-pass, 256 threads) ----------------------
__global__ void __launch_bounds__(256, 2) k_energy_tc() {
    extern __shared__ __align__(1024) char sm[];
    u32 sb = smem_u32(sm);
    int tid = threadIdx.x, wid = tid >> 5, lane = tid & 31;
    int wm = (wid >> 1) * 32, wn = (wid & 1) * 64;
    int ks = blockIdx.x, b = blockIdx.y;
    const f16* aH = g_xcH + ((size_t)b * K2C + 128) * N_ + ks * 128;
    const f16* aL = g_xL + (size_t)b * C_ * N_ + ks * 128;
    float acc[2][8][4] = {};
#pragma unroll 1
    for (int kc = 0; kc < 2; ++kc) {
        stA(sb + 0, aH + kc * 64, N_, tid);
        stA(sb + 16384, aL + kc * 64, N_, tid);
        CP_COMMIT();
        CP_WAIT0();
        __syncthreads();
        chunk_sym(sb + 0, sb + 16384, wm, wn, lane, acc);
        __syncthreads();
    }
    float* out = g_epart + ((size_t)(ks * B_ + b) * C_) * C_;
#pragma unroll
    for (int mf = 0; mf < 2; ++mf) {
        int r = wm + mf * 16 + (lane >> 2);
#pragma unroll
        for (int nf = 0; nf < 8; ++nf) {
            int c = wn + nf * 8 + (lane & 3) * 2;
            const float* a = acc[mf][nf];
            *reinterpret_cast<float2*>(out + r * C_ + c) = make_float2(a[0], a[1]);
            *reinterpret_cast<float2*>(out + (r + 8) * C_ + c) = make_float2(a[2], a[3]);
        }
    }
}

// ---------------- softmax(-energy) -> att f16 --------------------------------
__global__ void __launch_bounds__(128) k_softmax() {
    int warp = threadIdx.x >> 5, lane = threadIdx.x & 31;
    int row = blockIdx.x * 4 + warp;
    int b = row >> 7, c = row & 127;
    float e[4];
#pragma unroll
    for (int q = 0; q < 4; ++q) {
        int d = lane + q * 32;
        float s = 0.0f;
#pragma unroll
        for (int p = 0; p < KSPLIT; ++p)
            s += g_epart[((p * B_ + b) * C_ + c) * C_ + d];
        e[q] = -s;
    }
    float m = fmaxf(fmaxf(e[0], e[1]), fmaxf(e[2], e[3]));
#pragma unroll
    for (int off = 16; off > 0; off >>= 1)
        m = fmaxf(m, __shfl_xor_sync(0xffffffffu, m, off));
    float p4[4], s = 0.0f;
#pragma unroll
    for (int q = 0; q < 4; ++q) {
        p4[q] = __expf(e[q] - m);
        s += p4[q];
    }
#pragma unroll
    for (int off = 16; off > 0; off >>= 1)
        s += __shfl_xor_sync(0xffffffffu, s, off);
    float inv = 1.0f / s;
#pragma unroll
    for (int q = 0; q < 4; ++q)
        g_attH[(b * C_ + c) * C_ + lane + q * 32] =
            __float2half_rn(p4[q] * inv);
}

// ---------------- x_glb = gamma*(att @ x) + x -> xc rows 0..127 --------------
__global__ void __launch_bounds__(256, 2) k_xglb_tc(const float* __restrict__ x,
                                                    const float* __restrict__ gamma) {
    extern __shared__ __align__(1024) char sm[];
    u32 sb = smem_u32(sm);
    int tid = threadIdx.x, wid = tid >> 5, lane = tid & 31;
    int wm = (wid >> 1) * 32, wn = (wid & 1) * 64;
    int n0 = blockIdx.x * 128, b = blockIdx.y;
    const f16* aH = g_attH + (size_t)b * C_ * C_;
    const f16* bH = g_xcH + ((size_t)b * K2C + 128) * N_ + n0;
    float acc[2][8][4] = {};
    gemm_sp(sb, aH, C_, bH, N_, 2, tid, wm, wn, lane, acc);
    float gm = *gamma;
    const float* xb = x + (size_t)b * C_ * N_;
    f16* oH = g_xcH + (size_t)b * K2C * N_;
#pragma unroll
    for (int mf = 0; mf < 2; ++mf) {
        int r = wm + mf * 16 + (lane >> 2);
#pragma unroll
        for (int nf = 0; nf < 8; ++nf) {
            int c = wn + nf * 8 + (lane & 3) * 2;
            const float* a = acc[mf][nf];
#pragma unroll
            for (int hrow = 0; hrow < 2; ++hrow) {
                int rr = r + hrow * 8;
                float v0 = fmaf(gm, a[hrow * 2 + 0], xb[(size_t)rr * N_ + n0 + c]);
                float v1 = fmaf(gm, a[hrow * 2 + 1], xb[(size_t)rr * N_ + n0 + c + 1]);
                *reinterpret_cast<u32*>(oH + (size_t)rr * N_ + n0 + c) =
                    packh2(__float2half_rn(v0), __float2half_rn(v1));
            }
        }
    }
}

// ---------------- adj: 1 CTA/SM, warp tile 64x64, CTA 128m x 256n -------------
// smem: A resident (4 chunks, 64KB at 0..64K); B double buffer at 64K/96K,
// each B chunk = two 64k x 128n sub-tiles (+0, +16K).
__global__ void __launch_bounds__(256, 1) k_adj_tc(const float* __restrict__ b_adj) {
    extern __shared__ __align__(1024) char sm[];
    u32 sb = smem_u32(sm);
    int tid = threadIdx.x, wid = tid >> 5, lane = tid & 31;
    int wm = (wid & 1) * 64;          // 2 m positions
    int wn = (wid >> 1) * 64;         // 4 n positions (0..192)
    int n0 = blockIdx.x * 256, m0 = blockIdx.y * 128, b = blockIdx.z;
    const f16* aH = g_wadjH + (size_t)m0 * K2C;
    const f16* bH = g_xcH + (size_t)b * K2C * N_ + n0;

    // prologue: all 4 A chunks + B chunk 0 (both halves); then B chunk 1
#pragma unroll
    for (int c = 0; c < 4; ++c) stA(sb + c * 16384, aH + c * 64, K2C, tid);
    stB(sb + 65536, bH, N_, tid);
    stB(sb + 65536 + 16384, bH + 128, N_, tid);
    CP_COMMIT();
    stB(sb + 98304, bH + (size_t)64 * N_, N_, tid);
    stB(sb + 98304 + 16384, bH + (size_t)64 * N_ + 128, N_, tid);
    CP_COMMIT();

    float acc[4][8][4] = {};
    u32 sBl = sb + 65536 + (wn >> 7) * 16384;   // sub-tile by n-half
    int wnl = wn & 127;
#pragma unroll 1
    for (int kc = 0; kc < 4; ++kc) {
        if (kc + 1 < 4) CP_WAIT1(); else CP_WAIT0();
        __syncthreads();
        chunk64(sb + kc * 16384, sBl + (kc & 1) * 32768, wm, wnl, lane, acc);
        __syncthreads();
        if (kc + 2 < 4) {
            u32 dst = sb + 65536 + (kc & 1) * 32768;
            const f16* src = bH + (size_t)(kc + 2) * 64 * N_;
            stB(dst, src, N_, tid);
            stB(dst + 16384, src + 128, N_, tid);
            CP_COMMIT();
        }
    }

    f16* oH = g_adjH + (size_t)b * N_ * N_;
#pragma unroll
    for (int mf = 0; mf < 4; ++mf) {
        int r = wm + mf * 16 + (lane >> 2);
#pragma unroll
        for (int nf = 0; nf < 8; ++nf) {
            int c = wn + nf * 8 + (lane & 3) * 2;
            const float* a = acc[mf][nf];
#pragma unroll
            for (int hrow = 0; hrow < 2; ++hrow) {
                int rr = r + hrow * 8;
                float bias = b_adj[m0 + rr];
                *reinterpret_cast<u32*>(oH + (size_t)(m0 + rr) * N_ + n0 + c) =
                    packh2(__float2half_rn(sigm(a[hrow * 2 + 0] + bias)),
                           __float2half_rn(sigm(a[hrow * 2 + 1] + bias)));
            }
        }
    }
}

// ---------------- fused y1+y2: out = leaky(w_dyn @ leaky(x @ adj) + b) --------
__global__ void __launch_bounds__(256, 2) k_y1y2_tc(const float* __restrict__ b_dyn,
                                                    float* __restrict__ out) {
    extern __shared__ __align__(1024) char sm[];
    u32 sb = smem_u32(sm);
    int tid = threadIdx.x, wid = tid >> 5, lane = tid & 31;
    int wm = (wid >> 1) * 32, wn = (wid & 1) * 64;
    int n0 = blockIdx.x * 128, b = blockIdx.y;
    const f16* aH = g_xcH + ((size_t)b * K2C + 128) * N_;  // x rows, k contig
    const f16* bH = g_adjH + (size_t)b * N_ * N_ + n0;

    // --- y1 mainloop: acc = x @ adj tile ---
    float acc[2][8][4] = {};
    gemm_sp(sb, aH, N_, bH, N_, 32, tid, wm, wn, lane, acc);

    // --- write leaky(y1) into smem in B layout (two 64k x 128n chunks) ---
#pragma unroll
    for (int mf = 0; mf < 2; ++mf) {
        int r = wm + mf * 16 + (lane >> 2);
#pragma unroll
        for (int nf = 0; nf < 8; ++nf) {
            int c = wn + nf * 8 + (lane & 3) * 2;
            const float* a = acc[mf][nf];
#pragma unroll
            for (int hrow = 0; hrow < 2; ++hrow) {
                int rr = r + hrow * 8;
                u32 v = packh2(__float2half_rn(leaky(a[hrow * 2 + 0])),
                               __float2half_rn(leaky(a[hrow * 2 + 1])));
                int kr = rr & 63, ch = c >> 3;
                u32 addr = sb + 65536 + (rr >> 6) * 16384 + kr * 256 +
                           ((ch ^ (kr & 15)) & 15) * 16 + (c & 7) * 2;
                asm volatile("st.shared.b32 [%0], %1;" :: "r"(addr), "r"(v));
            }
        }
    }
    // stage w_dyn as A (2 chunks) into the now-free main A buffers
    stA(sb + SM_A(0), g_wdynH, C_, tid);
    stA(sb + SM_A(1), g_wdynH + 64, C_, tid);
    CP_COMMIT();
    CP_WAIT0();
    __syncthreads();

    // --- y2: acc2 = w_dyn @ y1_tile ---
    float acc2[2][8][4] = {};
    chunk_sp(sb + SM_A(0), sb + 65536, wm, wn, lane, acc2);
    chunk_sp(sb + SM_A(1), sb + 81920, wm, wn, lane, acc2);

    float* ob = out + (size_t)b * C_ * N_;
#pragma unroll
    for (int mf = 0; mf < 2; ++mf) {
        int r = wm + mf * 16 + (lane >> 2);
#pragma unroll
        for (int nf = 0; nf < 8; ++nf) {
            int c = wn + nf * 8 + (lane & 3) * 2;
            const float* a = acc2[mf][nf];
#pragma unroll
            for (int hrow = 0; hrow < 2; ++hrow) {
                int rr = r + hrow * 8;
                float bias = b_dyn[rr];
                *reinterpret_cast<float2*>(ob + (size_t)rr * N_ + n0 + c) =
                    make_float2(leaky(a[hrow * 2 + 0] + bias),
                                leaky(a[hrow * 2 + 1] + bias));
            }
        }
    }
}

// ---------------- launch ----------------
extern "C" void kernel_launch(void* const* d_in, const int* in_sizes, int n_in,
                              void* d_out, int out_size) {
    const float* x     = (const float*)d_in[0];  // [8,128,2048]
    const float* w_adj = (const float*)d_in[1];  // [2048,256]
    const float* b_adj = (const float*)d_in[2];  // [2048]
    const float* w_dyn = (const float*)d_in[3];  // [128,128]
    const float* b_dyn = (const float*)d_in[4];  // [128]
    const float* gamma = (const float*)d_in[5];  // [1]
    float* out = (float*)d_out;                  // [8,128,2048]

    cudaFuncSetAttribute(k_energy_tc, cudaFuncAttributeMaxDynamicSharedMemorySize, SMEM_SZ);
    cudaFuncSetAttribute(k_xglb_tc, cudaFuncAttributeMaxDynamicSharedMemorySize, SMEM_SZ);
    cudaFuncSetAttribute(k_adj_tc, cudaFuncAttributeMaxDynamicSharedMemorySize, SMEM_SZ_ADJ);
    cudaFuncSetAttribute(k_y1y2_tc, cudaFuncAttributeMaxDynamicSharedMemorySize, SMEM_SZ_BIG);

    k_cvt<<<1024, 256>>>(w_adj, w_dyn, x);
    k_energy_tc<<<dim3(KSPLIT, B_), 256, SMEM_SZ>>>();
    k_softmax<<<256, 128>>>();
    k_xglb_tc<<<dim3(N_ / 128, B_), 256, SMEM_SZ>>>(x, gamma);
    k_adj_tc<<<dim3(N_ / 256, N_ / 128, B_), 256, SMEM_SZ_ADJ>>>(b_adj);
    k_y1y2_tc<<<dim3(N_ / 128, B_), 256, SMEM_SZ_BIG>>>(b_dyn, out);
}

// round 15
// speedup vs baseline: 1.2354x; 1.2354x over previous
#include <cuda_runtime.h>
#include <cuda_fp16.h>
#include <cstdint>
#include <math.h>

#define B_ 8
#define C_ 128
#define N_ 2048
#define K2C 256
#define KSPLIT 16
#define SLOPE 0.2f

typedef unsigned int u32;
typedef __half f16;

// ---------------- device scratch (allocation-free) ----------------
__device__ float g_epart[KSPLIT * B_ * C_ * C_];            // energy partials
__device__ f16 g_xcH[B_ * K2C * N_];                        // xc = [x_glb; x] hi
__device__ f16 g_xL[B_ * C_ * N_];                          // x lo (energy only)
__device__ f16 g_wadjH[N_ * K2C];
__device__ f16 g_wdynH[C_ * C_];
__device__ f16 g_attH[B_ * C_ * C_];
__device__ f16 g_adjH[(size_t)B_ * N_ * N_];

// ---------------- primitives ----------------
__device__ __forceinline__ u32 smem_u32(const void* p) {
    u32 a;
    asm("{ .reg .u64 t; cvta.to.shared.u64 t, %1; cvt.u32.u64 %0, t; }"
        : "=r"(a) : "l"(p));
    return a;
}
__device__ __forceinline__ void ldsm4(u32* r, u32 addr) {
    asm volatile("ldmatrix.sync.aligned.m8n8.x4.shared.b16 {%0,%1,%2,%3}, [%4];"
                 : "=r"(r[0]), "=r"(r[1]), "=r"(r[2]), "=r"(r[3]) : "r"(addr));
}
__device__ __forceinline__ void ldsm4t(u32* r, u32 addr) {
    asm volatile("ldmatrix.sync.aligned.m8n8.x4.trans.shared.b16 {%0,%1,%2,%3}, [%4];"
                 : "=r"(r[0]), "=r"(r[1]), "=r"(r[2]), "=r"(r[3]) : "r"(addr));
}
__device__ __forceinline__ void mma_f16(float* c, const u32* a, const u32* b) {
    asm volatile(
        "mma.sync.aligned.m16n8k16.row.col.f32.f16.f16.f32 "
        "{%0,%1,%2,%3}, {%4,%5,%6,%7}, {%8,%9}, {%0,%1,%2,%3};"
        : "+f"(c[0]), "+f"(c[1]), "+f"(c[2]), "+f"(c[3])
        : "r"(a[0]), "r"(a[1]), "r"(a[2]), "r"(a[3]), "r"(b[0]), "r"(b[1]));
}
__device__ __forceinline__ void cpa16(u32 dst, const void* src) {
    asm volatile("cp.async.cg.shared.global [%0], [%1], 16;" :: "r"(dst), "l"(src));
}
#define CP_COMMIT() asm volatile("cp.async.commit_group;" ::: "memory")
#define CP_WAIT1() asm volatile("cp.async.wait_group 1;" ::: "memory")
#define CP_WAIT0() asm volatile("cp.async.wait_group 0;" ::: "memory")

#define SWZ(o) ((o) ^ (((o) >> 3) & 0x70))

#define SMEM_SZ 65536        // energy (2 x 32KB scratch)
#define SMEM_SZ3 98304       // triple-buffered mainloop kernels + adj + y1y2

__device__ __forceinline__ void split1(float v, f16& h, f16& l) {
    h = __float2half_rn(v);
    l = __float2half_rn(v - __half2float(h));
}
__device__ __forceinline__ u32 packh2(f16 a, f16 b) {
    return (u32)__half_as_ushort(a) | ((u32)__half_as_ushort(b) << 16);
}
__device__ __forceinline__ float leaky(float v) { return v > 0.0f ? v : SLOPE * v; }
__device__ __forceinline__ float sigm(float v) { return 1.0f / (1.0f + __expf(-v)); }

// ---------------- staging (256 threads) ----------------
__device__ __forceinline__ void stA(u32 sbase, const f16* __restrict__ src,
                                    int lda, int tid) {
    int row = tid & 127, g = tid >> 7;
    const f16* p = src + (size_t)row * lda + g * 32;
#pragma unroll
    for (int i = 0; i < 4; ++i) {
        int ch = g * 4 + i;
        cpa16(sbase + (u32)SWZ(row * 128 + ch * 16), p + i * 8);
    }
}
__device__ __forceinline__ void stB(u32 sbase, const f16* __restrict__ src,
                                    int ldb, int tid) {
    int kr = tid >> 2, q = tid & 3;
    const f16* p = src + (size_t)kr * ldb + q * 32;
#pragma unroll
    for (int i = 0; i < 4; ++i) {
        int ch = q * 4 + i;
        cpa16(sbase + (u32)(kr * 256 + ((ch ^ (kr & 15)) & 15) * 16), p + i * 8);
    }
}

// ---- single-pass chunk (A f16, B f16 via trans). Warp tile 32x64. ----
__device__ __forceinline__ void chunk_sp(u32 sA, u32 sB, int wm, int wn,
                                         int lane, float acc[2][8][4]) {
#pragma unroll
    for (int s = 0; s < 4; ++s) {
        int k0 = s * 16;
        u32 ah[2][4];
        {
            int am = lane & 15, ak = k0 + (lane >> 4) * 8;
            ldsm4(ah[0], sA + (u32)SWZ((wm + am) * 128 + ak * 2));
            ldsm4(ah[1], sA + (u32)SWZ((wm + 16 + am) * 128 + ak * 2));
        }
#pragma unroll
        for (int g = 0; g < 4; ++g) {
            u32 bh[4];
            int t = lane >> 3, r = lane & 7;
            int k = k0 + (t & 1) * 8 + r;
            int nc = ((wn + g * 16) >> 3) + (t >> 1);
            ldsm4t(bh, sB + (u32)(k * 256 + ((nc ^ (k & 15)) & 15) * 16));
#pragma unroll
            for (int mf = 0; mf < 2; ++mf)
#pragma unroll
                for (int nf = 0; nf < 2; ++nf)
                    mma_f16(acc[mf][g * 2 + nf], ah[mf], bh + nf * 2);
        }
    }
}

// ---- energy chunk: 3-pass both-split, B frags from the A tiles ----
__device__ __forceinline__ void chunk_sym(u32 sAH, u32 sAL, int wm, int wn,
                                          int lane, float acc[2][8][4]) {
#pragma unroll
    for (int s = 0; s < 4; ++s) {
        int k0 = s * 16;
        u32 ah[2][4], al[2][4];
        {
            int am = lane & 15, ak = k0 + (lane >> 4) * 8;
            u32 o0 = (u32)SWZ((wm + am) * 128 + ak * 2);
            u32 o1 = (u32)SWZ((wm + 16 + am) * 128 + ak * 2);
            ldsm4(ah[0], sAH + o0);
            ldsm4(ah[1], sAH + o1);
            ldsm4(al[0], sAL + o0);
            ldsm4(al[1], sAL + o1);
        }
#pragma unroll
        for (int g = 0; g < 4; ++g) {
            u32 bh[4], bl[4];
            int t = lane >> 3, r = lane & 7;
            int n = wn + g * 16 + (t >> 1) * 8 + r;
            int k = k0 + (t & 1) * 8;
            u32 boff = (u32)SWZ(n * 128 + k * 2);
            ldsm4(bh, sAH + boff);
            ldsm4(bl, sAL + boff);
#pragma unroll
            for (int mf = 0; mf < 2; ++mf)
#pragma unroll
                for (int nf = 0; nf < 2; ++nf) {
                    float* c = acc[mf][g * 2 + nf];
                    mma_f16(c, ah[mf], bh + nf * 2);
                    mma_f16(c, ah[mf], bl + nf * 2);
                    mma_f16(c, al[mf], bh + nf * 2);
                }
        }
    }
}

// Triple-buffered mainloop: ONE barrier per chunk. Buffer b at b*32768:
// A at +0 (16KB), B at +16384 (16KB). stage(kc+2) -> buf (kc+2)%3, never
// conflicting with buf kc%3 (being read) or (kc+1)%3 (next read).
__device__ __forceinline__ void gemm_sp3(u32 sb, const f16* aH, int lda,
                                         const f16* bH, int ldb, int nc_total,
                                         int tid, int wm, int wn, int lane,
                                         float acc[2][8][4]) {
    stA(sb + 0, aH, lda, tid);
    stB(sb + 16384, bH, ldb, tid);
    CP_COMMIT();
    if (nc_total > 1) {
        stA(sb + 32768, aH + 64, lda, tid);
        stB(sb + 49152, bH + (size_t)64 * ldb, ldb, tid);
        CP_COMMIT();
    }
#pragma unroll 1
    for (int kc = 0; kc < nc_total; ++kc) {
        if (kc + 1 < nc_total) CP_WAIT1(); else CP_WAIT0();
        __syncthreads();
        u32 base = sb + (u32)(kc % 3) * 32768;
        chunk_sp(base, base + 16384, wm, wn, lane, acc);
        if (kc + 2 < nc_total) {
            u32 nbase = sb + (u32)((kc + 2) % 3) * 32768;
            stA(nbase, aH + (size_t)(kc + 2) * 64, lda, tid);
            stB(nbase + 16384, bH + (size_t)(kc + 2) * 64 * ldb, ldb, tid);
            CP_COMMIT();
        }
    }
}

// ---------------- pre-pass: convert weights + x to f16 -----------------------
__global__ void k_cvt(const float* __restrict__ w_adj,
                      const float* __restrict__ w_dyn,
                      const float* __restrict__ x) {
    int i0 = blockIdx.x * blockDim.x + threadIdx.x;
    int st = gridDim.x * blockDim.x;
    for (int i = i0; i < N_ * K2C; i += st)
        g_wadjH[i] = __float2half_rn(w_adj[i]);
    for (int i = i0; i < C_ * C_; i += st)
        g_wdynH[i] = __float2half_rn(w_dyn[i]);
    for (int i = i0; i < B_ * C_ * N_; i += st) {
        int b = i / (C_ * N_);
        int rem = i - b * C_ * N_;
        f16 h, l;
        split1(x[i], h, l);
        g_xcH[(size_t)b * K2C * N_ + 128 * N_ + rem] = h;  // xc rows 128..255 = x
        g_xL[i] = l;                                       // lo kept for energy
    }
}

// ---------------- energy partials (3-pass, 256 threads) ----------------------
__global__ void __launch_bounds__(256, 2) k_energy_tc() {
    extern __shared__ __align__(1024) char sm[];
    u32 sb = smem_u32(sm);
    int tid = threadIdx.x, wid = tid >> 5, lane = tid & 31;
    int wm = (wid >> 1) * 32, wn = (wid & 1) * 64;
    int ks = blockIdx.x, b = blockIdx.y;
    const f16* aH = g_xcH + ((size_t)b * K2C + 128) * N_ + ks * 128;
    const f16* aL = g_xL + (size_t)b * C_ * N_ + ks * 128;
    float acc[2][8][4] = {};
#pragma unroll 1
    for (int kc = 0; kc < 2; ++kc) {
        stA(sb + 0, aH + kc * 64, N_, tid);
        stA(sb + 16384, aL + kc * 64, N_, tid);
        CP_COMMIT();
        CP_WAIT0();
        __syncthreads();
        chunk_sym(sb + 0, sb + 16384, wm, wn, lane, acc);
        __syncthreads();
    }
    float* out = g_epart + ((size_t)(ks * B_ + b) * C_) * C_;
#pragma unroll
    for (int mf = 0; mf < 2; ++mf) {
        int r = wm + mf * 16 + (lane >> 2);
#pragma unroll
        for (int nf = 0; nf < 8; ++nf) {
            int c = wn + nf * 8 + (lane & 3) * 2;
            const float* a = acc[mf][nf];
            *reinterpret_cast<float2*>(out + r * C_ + c) = make_float2(a[0], a[1]);
            *reinterpret_cast<float2*>(out + (r + 8) * C_ + c) = make_float2(a[2], a[3]);
        }
    }
}

// ---------------- softmax(-energy) -> att f16 --------------------------------
__global__ void __launch_bounds__(128) k_softmax() {
    int warp = threadIdx.x >> 5, lane = threadIdx.x & 31;
    int row = blockIdx.x * 4 + warp;
    int b = row >> 7, c = row & 127;
    float e[4];
#pragma unroll
    for (int q = 0; q < 4; ++q) {
        int d = lane + q * 32;
        float s = 0.0f;
#pragma unroll
        for (int p = 0; p < KSPLIT; ++p)
            s += g_epart[((p * B_ + b) * C_ + c) * C_ + d];
        e[q] = -s;
    }
    float m = fmaxf(fmaxf(e[0], e[1]), fmaxf(e[2], e[3]));
#pragma unroll
    for (int off = 16; off > 0; off >>= 1)
        m = fmaxf(m, __shfl_xor_sync(0xffffffffu, m, off));
    float p4[4], s = 0.0f;
#pragma unroll
    for (int q = 0; q < 4; ++q) {
        p4[q] = __expf(e[q] - m);
        s += p4[q];
    }
#pragma unroll
    for (int off = 16; off > 0; off >>= 1)
        s += __shfl_xor_sync(0xffffffffu, s, off);
    float inv = 1.0f / s;
#pragma unroll
    for (int q = 0; q < 4; ++q)
        g_attH[(b * C_ + c) * C_ + lane + q * 32] =
            __float2half_rn(p4[q] * inv);
}

// ---------------- x_glb = gamma*(att @ x) + x -> xc rows 0..127 --------------
__global__ void __launch_bounds__(256, 2) k_xglb_tc(const float* __restrict__ x,
                                                    const float* __restrict__ gamma) {
    extern __shared__ __align__(1024) char sm[];
    u32 sb = smem_u32(sm);
    int tid = threadIdx.x, wid = tid >> 5, lane = tid & 31;
    int wm = (wid >> 1) * 32, wn = (wid & 1) * 64;
    int n0 = blockIdx.x * 128, b = blockIdx.y;
    const f16* aH = g_attH + (size_t)b * C_ * C_;
    const f16* bH = g_xcH + ((size_t)b * K2C + 128) * N_ + n0;
    float acc[2][8][4] = {};
    gemm_sp3(sb, aH, C_, bH, N_, 2, tid, wm, wn, lane, acc);
    float gm = *gamma;
    const float* xb = x + (size_t)b * C_ * N_;
    f16* oH = g_xcH + (size_t)b * K2C * N_;
#pragma unroll
    for (int mf = 0; mf < 2; ++mf) {
        int r = wm + mf * 16 + (lane >> 2);
#pragma unroll
        for (int nf = 0; nf < 8; ++nf) {
            int c = wn + nf * 8 + (lane & 3) * 2;
            const float* a = acc[mf][nf];
#pragma unroll
            for (int hrow = 0; hrow < 2; ++hrow) {
                int rr = r + hrow * 8;
                float v0 = fmaf(gm, a[hrow * 2 + 0], xb[(size_t)rr * N_ + n0 + c]);
                float v1 = fmaf(gm, a[hrow * 2 + 1], xb[(size_t)rr * N_ + n0 + c + 1]);
                *reinterpret_cast<u32*>(oH + (size_t)rr * N_ + n0 + c) =
                    packh2(__float2half_rn(v0), __float2half_rn(v1));
            }
        }
    }
}

// ---------------- adj: A-resident, 2 n-tiles per CTA (R13 form) ---------------
// smem: A chunks resident at 0,16K,32K,48K; B double buffer at 64K, 80K.
__global__ void __launch_bounds__(256, 2) k_adj_tc(const float* __restrict__ b_adj) {
    extern __shared__ __align__(1024) char sm[];
    u32 sb = smem_u32(sm);
    int tid = threadIdx.x, wid = tid >> 5, lane = tid & 31;
    int wm = (wid >> 1) * 32, wn = (wid & 1) * 64;
    int n0base = blockIdx.x * 256, m0 = blockIdx.y * 128, b = blockIdx.z;
    const f16* aH = g_wadjH + (size_t)m0 * K2C;
    const f16* bH = g_xcH + (size_t)b * K2C * N_ + n0base;

#pragma unroll
    for (int c = 0; c < 4; ++c) stA(sb + c * 16384, aH + c * 64, K2C, tid);
    stB(sb + 65536, bH, N_, tid);
    CP_COMMIT();
    stB(sb + 81920, bH + (size_t)64 * N_, N_, tid);
    CP_COMMIT();

    f16* oH = g_adjH + (size_t)b * N_ * N_;
#pragma unroll 1
    for (int nt = 0; nt < 2; ++nt) {
        float acc[2][8][4] = {};
#pragma unroll 1
        for (int kc = 0; kc < 4; ++kc) {
            int t = nt * 4 + kc;
            if (t + 1 < 8) CP_WAIT1(); else CP_WAIT0();
            __syncthreads();
            chunk_sp(sb + kc * 16384, sb + 65536 + (t & 1) * 16384, wm, wn,
                     lane, acc);
            __syncthreads();
            if (t + 2 < 8) {
                int t2 = t + 2;
                stB(sb + 65536 + (t & 1) * 16384,
                    bH + (size_t)(t2 & 3) * 64 * N_ + (t2 >> 2) * 128, N_, tid);
                CP_COMMIT();
            }
        }
        int n0 = n0base + nt * 128;
#pragma unroll
        for (int mf = 0; mf < 2; ++mf) {
            int r = wm + mf * 16 + (lane >> 2);
#pragma unroll
            for (int nf = 0; nf < 8; ++nf) {
                int c = wn + nf * 8 + (lane & 3) * 2;
                const float* a = acc[mf][nf];
#pragma unroll
                for (int hrow = 0; hrow < 2; ++hrow) {
                    int rr = r + hrow * 8;
                    float bias = b_adj[m0 + rr];
                    *reinterpret_cast<u32*>(oH + (size_t)(m0 + rr) * N_ + n0 + c) =
                        packh2(__float2half_rn(sigm(a[hrow * 2 + 0] + bias)),
                               __float2half_rn(sigm(a[hrow * 2 + 1] + bias)));
                }
            }
        }
    }
}

// ---------------- fused y1+y2: out = leaky(w_dyn @ leaky(x @ adj) + b) --------
// mainloop: triple buffers 0/32K/64K. After it: y1 stash at 0 & 16K (B layout),
// w_dyn A chunks at 32K & 48K.
__global__ void __launch_bounds__(256, 2) k_y1y2_tc(const float* __restrict__ b_dyn,
                                                    float* __restrict__ out) {
    extern __shared__ __align__(1024) char sm[];
    u32 sb = smem_u32(sm);
    int tid = threadIdx.x, wid = tid >> 5, lane = tid & 31;
    int wm = (wid >> 1) * 32, wn = (wid & 1) * 64;
    int n0 = blockIdx.x * 128, b = blockIdx.y;
    const f16* aH = g_xcH + ((size_t)b * K2C + 128) * N_;  // x rows, k contig
    const f16* bH = g_adjH + (size_t)b * N_ * N_ + n0;

    // --- y1 mainloop: acc = x @ adj tile ---
    float acc[2][8][4] = {};
    gemm_sp3(sb, aH, N_, bH, N_, 32, tid, wm, wn, lane, acc);
    __syncthreads();  // all warps done with all buffers before reuse

    // --- write leaky(y1) into smem B-layout: 64k-chunks at 0 and 16384 ---
#pragma unroll
    for (int mf = 0; mf < 2; ++mf) {
        int r = wm + mf * 16 + (lane >> 2);
#pragma unroll
        for (int nf = 0; nf < 8; ++nf) {
            int c = wn + nf * 8 + (lane & 3) * 2;
            const float* a = acc[mf][nf];
#pragma unroll
            for (int hrow = 0; hrow < 2; ++hrow) {
                int rr = r + hrow * 8;
                u32 v = packh2(__float2half_rn(leaky(a[hrow * 2 + 0])),
                               __float2half_rn(leaky(a[hrow * 2 + 1])));
                int kr = rr & 63, ch = c >> 3;
                u32 addr = sb + (rr >> 6) * 16384 + kr * 256 +
                           ((ch ^ (kr & 15)) & 15) * 16 + (c & 7) * 2;
                asm volatile("st.shared.b32 [%0], %1;" :: "r"(addr), "r"(v));
            }
        }
    }
    // stage w_dyn as A (2 chunks) into buffer 1 region
    stA(sb + 32768, g_wdynH, C_, tid);
    stA(sb + 49152, g_wdynH + 64, C_, tid);
    CP_COMMIT();
    CP_WAIT0();
    __syncthreads();

    // --- y2: acc2 = w_dyn @ y1_tile ---
    float acc2[2][8][4] = {};
    chunk_sp(sb + 32768, sb + 0, wm, wn, lane, acc2);
    chunk_sp(sb + 49152, sb + 16384, wm, wn, lane, acc2);

    float* ob = out + (size_t)b * C_ * N_;
#pragma unroll
    for (int mf = 0; mf < 2; ++mf) {
        int r = wm + mf * 16 + (lane >> 2);
#pragma unroll
        for (int nf = 0; nf < 8; ++nf) {
            int c = wn + nf * 8 + (lane & 3) * 2;
            const float* a = acc2[mf][nf];
#pragma unroll
            for (int hrow = 0; hrow < 2; ++hrow) {
                int rr = r + hrow * 8;
                float bias = b_dyn[rr];
                *reinterpret_cast<float2*>(ob + (size_t)rr * N_ + n0 + c) =
                    make_float2(leaky(a[hrow * 2 + 0] + bias),
                                leaky(a[hrow * 2 + 1] + bias));
            }
        }
    }
}

// ---------------- launch ----------------
extern "C" void kernel_launch(void* const* d_in, const int* in_sizes, int n_in,
                              void* d_out, int out_size) {
    const float* x     = (const float*)d_in[0];  // [8,128,2048]
    const float* w_adj = (const float*)d_in[1];  // [2048,256]
    const float* b_adj = (const float*)d_in[2];  // [2048]
    const float* w_dyn = (const float*)d_in[3];  // [128,128]
    const float* b_dyn = (const float*)d_in[4];  // [128]
    const float* gamma = (const float*)d_in[5];  // [1]
    float* out = (float*)d_out;                  // [8,128,2048]

    cudaFuncSetAttribute(k_energy_tc, cudaFuncAttributeMaxDynamicSharedMemorySize, SMEM_SZ);
    cudaFuncSetAttribute(k_xglb_tc, cudaFuncAttributeMaxDynamicSharedMemorySize, SMEM_SZ3);
    cudaFuncSetAttribute(k_adj_tc, cudaFuncAttributeMaxDynamicSharedMemorySize, SMEM_SZ3);
    cudaFuncSetAttribute(k_y1y2_tc, cudaFuncAttributeMaxDynamicSharedMemorySize, SMEM_SZ3);

    k_cvt<<<1024, 256>>>(w_adj, w_dyn, x);
    k_energy_tc<<<dim3(KSPLIT, B_), 256, SMEM_SZ>>>();
    k_softmax<<<256, 128>>>();
    k_xglb_tc<<<dim3(N_ / 128, B_), 256, SMEM_SZ3>>>(x, gamma);
    k_adj_tc<<<dim3(N_ / 256, N_ / 128, B_), 256, SMEM_SZ3>>>(b_adj);
    k_y1y2_tc<<<dim3(N_ / 128, B_), 256, SMEM_SZ3>>>(b_dyn, out);
}

// round 16
// speedup vs baseline: 1.3705x; 1.1094x over previous
#include <cuda_runtime.h>
#include <cuda_fp16.h>
#include <cstdint>
#include <math.h>

#define B_ 8
#define C_ 128
#define N_ 2048
#define K2C 256
#define KSPLIT 16
#define SLOPE 0.2f

typedef unsigned int u32;
typedef __half f16;

// ---------------- device scratch (allocation-free) ----------------
__device__ float g_epart[KSPLIT * B_ * C_ * C_];            // energy partials
__device__ f16 g_xcH[B_ * K2C * N_];                        // xc = [x_glb; x] hi
__device__ f16 g_xL[B_ * C_ * N_];                          // x lo (energy only)
__device__ f16 g_wadjH[N_ * K2C];
__device__ f16 g_wdynH[C_ * C_];
__device__ f16 g_attH[B_ * C_ * C_];
__device__ f16 g_adjH[(size_t)B_ * N_ * N_];

// ---------------- primitives ----------------
__device__ __forceinline__ u32 smem_u32(const void* p) {
    u32 a;
    asm("{ .reg .u64 t; cvta.to.shared.u64 t, %1; cvt.u32.u64 %0, t; }"
        : "=r"(a) : "l"(p));
    return a;
}
__device__ __forceinline__ void ldsm4(u32* r, u32 addr) {
    asm volatile("ldmatrix.sync.aligned.m8n8.x4.shared.b16 {%0,%1,%2,%3}, [%4];"
                 : "=r"(r[0]), "=r"(r[1]), "=r"(r[2]), "=r"(r[3]) : "r"(addr));
}
__device__ __forceinline__ void ldsm4t(u32* r, u32 addr) {
    asm volatile("ldmatrix.sync.aligned.m8n8.x4.trans.shared.b16 {%0,%1,%2,%3}, [%4];"
                 : "=r"(r[0]), "=r"(r[1]), "=r"(r[2]), "=r"(r[3]) : "r"(addr));
}
__device__ __forceinline__ void mma_f16(float* c, const u32* a, const u32* b) {
    asm volatile(
        "mma.sync.aligned.m16n8k16.row.col.f32.f16.f16.f32 "
        "{%0,%1,%2,%3}, {%4,%5,%6,%7}, {%8,%9}, {%0,%1,%2,%3};"
        : "+f"(c[0]), "+f"(c[1]), "+f"(c[2]), "+f"(c[3])
        : "r"(a[0]), "r"(a[1]), "r"(a[2]), "r"(a[3]), "r"(b[0]), "r"(b[1]));
}
__device__ __forceinline__ void cpa16(u32 dst, const void* src) {
    asm volatile("cp.async.cg.shared.global [%0], [%1], 16;" :: "r"(dst), "l"(src));
}
#define CP_COMMIT() asm volatile("cp.async.commit_group;" ::: "memory")
#define CP_WAIT1() asm volatile("cp.async.wait_group 1;" ::: "memory")
#define CP_WAIT0() asm volatile("cp.async.wait_group 0;" ::: "memory")

#define SWZ(o) ((o) ^ (((o) >> 3) & 0x70))

#define SMEM_SZ 65536        // energy (2 x 32KB scratch)
#define SMEM_SZ3 98304       // triple-buffered mainloop kernels + adj + y1y2

__device__ __forceinline__ void split1(float v, f16& h, f16& l) {
    h = __float2half_rn(v);
    l = __float2half_rn(v - __half2float(h));
}
__device__ __forceinline__ u32 packh2(f16 a, f16 b) {
    return (u32)__half_as_ushort(a) | ((u32)__half_as_ushort(b) << 16);
}
__device__ __forceinline__ float leaky(float v) { return v > 0.0f ? v : SLOPE * v; }

// packed sigmoid: sig(x) = 0.5*tanh(0.5x) + 0.5, via tanh.approx.f16x2
// (1 MUFU per 2 elements instead of 2 MUFU per element)
__device__ __forceinline__ u32 sigm2(float v0, float v1) {
    __half2 hv = __floats2half2_rn(0.5f * v0, 0.5f * v1);
    u32 hin = *reinterpret_cast<u32*>(&hv);
    u32 t;
    asm("tanh.approx.f16x2 %0, %1;" : "=r"(t) : "r"(hin));
    __half2 th = *reinterpret_cast<__half2*>(&t);
    __half2 half_c = __float2half2_rn(0.5f);
    __half2 y = __hfma2(th, half_c, half_c);
    return *reinterpret_cast<u32*>(&y);
}

// ---------------- staging (256 threads) ----------------
__device__ __forceinline__ void stA(u32 sbase, const f16* __restrict__ src,
                                    int lda, int tid) {
    int row = tid & 127, g = tid >> 7;
    const f16* p = src + (size_t)row * lda + g * 32;
#pragma unroll
    for (int i = 0; i < 4; ++i) {
        int ch = g * 4 + i;
        cpa16(sbase + (u32)SWZ(row * 128 + ch * 16), p + i * 8);
    }
}
__device__ __forceinline__ void stB(u32 sbase, const f16* __restrict__ src,
                                    int ldb, int tid) {
    int kr = tid >> 2, q = tid & 3;
    const f16* p = src + (size_t)kr * ldb + q * 32;
#pragma unroll
    for (int i = 0; i < 4; ++i) {
        int ch = q * 4 + i;
        cpa16(sbase + (u32)(kr * 256 + ((ch ^ (kr & 15)) & 15) * 16), p + i * 8);
    }
}

// ---- single-pass chunk (A f16, B f16 via trans). Warp tile 32x64. ----
__device__ __forceinline__ void chunk_sp(u32 sA, u32 sB, int wm, int wn,
                                         int lane, float acc[2][8][4]) {
#pragma unroll
    for (int s = 0; s < 4; ++s) {
        int k0 = s * 16;
        u32 ah[2][4];
        {
            int am = lane & 15, ak = k0 + (lane >> 4) * 8;
            ldsm4(ah[0], sA + (u32)SWZ((wm + am) * 128 + ak * 2));
            ldsm4(ah[1], sA + (u32)SWZ((wm + 16 + am) * 128 + ak * 2));
        }
#pragma unroll
        for (int g = 0; g < 4; ++g) {
            u32 bh[4];
            int t = lane >> 3, r = lane & 7;
            int k = k0 + (t & 1) * 8 + r;
            int nc = ((wn + g * 16) >> 3) + (t >> 1);
            ldsm4t(bh, sB + (u32)(k * 256 + ((nc ^ (k & 15)) & 15) * 16));
#pragma unroll
            for (int mf = 0; mf < 2; ++mf)
#pragma unroll
                for (int nf = 0; nf < 2; ++nf)
                    mma_f16(acc[mf][g * 2 + nf], ah[mf], bh + nf * 2);
        }
    }
}

// ---- energy chunk: 3-pass both-split, B frags from the A tiles ----
__device__ __forceinline__ void chunk_sym(u32 sAH, u32 sAL, int wm, int wn,
                                          int lane, float acc[2][8][4]) {
#pragma unroll
    for (int s = 0; s < 4; ++s) {
        int k0 = s * 16;
        u32 ah[2][4], al[2][4];
        {
            int am = lane & 15, ak = k0 + (lane >> 4) * 8;
            u32 o0 = (u32)SWZ((wm + am) * 128 + ak * 2);
            u32 o1 = (u32)SWZ((wm + 16 + am) * 128 + ak * 2);
            ldsm4(ah[0], sAH + o0);
            ldsm4(ah[1], sAH + o1);
            ldsm4(al[0], sAL + o0);
            ldsm4(al[1], sAL + o1);
        }
#pragma unroll
        for (int g = 0; g < 4; ++g) {
            u32 bh[4], bl[4];
            int t = lane >> 3, r = lane & 7;
            int n = wn + g * 16 + (t >> 1) * 8 + r;
            int k = k0 + (t & 1) * 8;
            u32 boff = (u32)SWZ(n * 128 + k * 2);
            ldsm4(bh, sAH + boff);
            ldsm4(bl, sAL + boff);
#pragma unroll
            for (int mf = 0; mf < 2; ++mf)
#pragma unroll
                for (int nf = 0; nf < 2; ++nf) {
                    float* c = acc[mf][g * 2 + nf];
                    mma_f16(c, ah[mf], bh + nf * 2);
                    mma_f16(c, ah[mf], bl + nf * 2);
                    mma_f16(c, al[mf], bh + nf * 2);
                }
        }
    }
}

// Triple-buffered mainloop: ONE barrier per chunk.
__device__ __forceinline__ void gemm_sp3(u32 sb, const f16* aH, int lda,
                                         const f16* bH, int ldb, int nc_total,
                                         int tid, int wm, int wn, int lane,
                                         float acc[2][8][4]) {
    stA(sb + 0, aH, lda, tid);
    stB(sb + 16384, bH, ldb, tid);
    CP_COMMIT();
    if (nc_total > 1) {
        stA(sb + 32768, aH + 64, lda, tid);
        stB(sb + 49152, bH + (size_t)64 * ldb, ldb, tid);
        CP_COMMIT();
    }
#pragma unroll 1
    for (int kc = 0; kc < nc_total; ++kc) {
        if (kc + 1 < nc_total) CP_WAIT1(); else CP_WAIT0();
        __syncthreads();
        u32 base = sb + (u32)(kc % 3) * 32768;
        chunk_sp(base, base + 16384, wm, wn, lane, acc);
        if (kc + 2 < nc_total) {
            u32 nbase = sb + (u32)((kc + 2) % 3) * 32768;
            stA(nbase, aH + (size_t)(kc + 2) * 64, lda, tid);
            stB(nbase + 16384, bH + (size_t)(kc + 2) * 64 * ldb, ldb, tid);
            CP_COMMIT();
        }
    }
}

// ---------------- pre-pass: convert weights + x to f16 -----------------------
__global__ void k_cvt(const float* __restrict__ w_adj,
                      const float* __restrict__ w_dyn,
                      const float* __restrict__ x) {
    int i0 = blockIdx.x * blockDim.x + threadIdx.x;
    int st = gridDim.x * blockDim.x;
    for (int i = i0; i < N_ * K2C; i += st)
        g_wadjH[i] = __float2half_rn(w_adj[i]);
    for (int i = i0; i < C_ * C_; i += st)
        g_wdynH[i] = __float2half_rn(w_dyn[i]);
    for (int i = i0; i < B_ * C_ * N_; i += st) {
        int b = i / (C_ * N_);
        int rem = i - b * C_ * N_;
        f16 h, l;
        split1(x[i], h, l);
        g_xcH[(size_t)b * K2C * N_ + 128 * N_ + rem] = h;  // xc rows 128..255 = x
        g_xL[i] = l;                                       // lo kept for energy
    }
}

// ---------------- energy partials (3-pass, 256 threads) ----------------------
__global__ void __launch_bounds__(256, 2) k_energy_tc() {
    extern __shared__ __align__(1024) char sm[];
    u32 sb = smem_u32(sm);
    int tid = threadIdx.x, wid = tid >> 5, lane = tid & 31;
    int wm = (wid >> 1) * 32, wn = (wid & 1) * 64;
    int ks = blockIdx.x, b = blockIdx.y;
    const f16* aH = g_xcH + ((size_t)b * K2C + 128) * N_ + ks * 128;
    const f16* aL = g_xL + (size_t)b * C_ * N_ + ks * 128;
    float acc[2][8][4] = {};
#pragma unroll 1
    for (int kc = 0; kc < 2; ++kc) {
        stA(sb + 0, aH + kc * 64, N_, tid);
        stA(sb + 16384, aL + kc * 64, N_, tid);
        CP_COMMIT();
        CP_WAIT0();
        __syncthreads();
        chunk_sym(sb + 0, sb + 16384, wm, wn, lane, acc);
        __syncthreads();
    }
    float* out = g_epart + ((size_t)(ks * B_ + b) * C_) * C_;
#pragma unroll
    for (int mf = 0; mf < 2; ++mf) {
        int r = wm + mf * 16 + (lane >> 2);
#pragma unroll
        for (int nf = 0; nf < 8; ++nf) {
            int c = wn + nf * 8 + (lane & 3) * 2;
            const float* a = acc[mf][nf];
            *reinterpret_cast<float2*>(out + r * C_ + c) = make_float2(a[0], a[1]);
            *reinterpret_cast<float2*>(out + (r + 8) * C_ + c) = make_float2(a[2], a[3]);
        }
    }
}

// ---------------- softmax(-energy) -> att f16 --------------------------------
__global__ void __launch_bounds__(128) k_softmax() {
    int warp = threadIdx.x >> 5, lane = threadIdx.x & 31;
    int row = blockIdx.x * 4 + warp;
    int b = row >> 7, c = row & 127;
    float e[4];
#pragma unroll
    for (int q = 0; q < 4; ++q) {
        int d = lane + q * 32;
        float s = 0.0f;
#pragma unroll
        for (int p = 0; p < KSPLIT; ++p)
            s += g_epart[((p * B_ + b) * C_ + c) * C_ + d];
        e[q] = -s;
    }
    float m = fmaxf(fmaxf(e[0], e[1]), fmaxf(e[2], e[3]));
#pragma unroll
    for (int off = 16; off > 0; off >>= 1)
        m = fmaxf(m, __shfl_xor_sync(0xffffffffu, m, off));
    float p4[4], s = 0.0f;
#pragma unroll
    for (int q = 0; q < 4; ++q) {
        p4[q] = __expf(e[q] - m);
        s += p4[q];
    }
#pragma unroll
    for (int off = 16; off > 0; off >>= 1)
        s += __shfl_xor_sync(0xffffffffu, s, off);
    float inv = 1.0f / s;
#pragma unroll
    for (int q = 0; q < 4; ++q)
        g_attH[(b * C_ + c) * C_ + lane + q * 32] =
            __float2half_rn(p4[q] * inv);
}

// ---------------- x_glb = gamma*(att @ x) + x -> xc rows 0..127 --------------
__global__ void __launch_bounds__(256, 2) k_xglb_tc(const float* __restrict__ x,
                                                    const float* __restrict__ gamma) {
    extern __shared__ __align__(1024) char sm[];
    u32 sb = smem_u32(sm);
    int tid = threadIdx.x, wid = tid >> 5, lane = tid & 31;
    int wm = (wid >> 1) * 32, wn = (wid & 1) * 64;
    int n0 = blockIdx.x * 128, b = blockIdx.y;
    const f16* aH = g_attH + (size_t)b * C_ * C_;
    const f16* bH = g_xcH + ((size_t)b * K2C + 128) * N_ + n0;
    float acc[2][8][4] = {};
    gemm_sp3(sb, aH, C_, bH, N_, 2, tid, wm, wn, lane, acc);
    float gm = *gamma;
    const float* xb = x + (size_t)b * C_ * N_;
    f16* oH = g_xcH + (size_t)b * K2C * N_;
#pragma unroll
    for (int mf = 0; mf < 2; ++mf) {
        int r = wm + mf * 16 + (lane >> 2);
#pragma unroll
        for (int nf = 0; nf < 8; ++nf) {
            int c = wn + nf * 8 + (lane & 3) * 2;
            const float* a = acc[mf][nf];
#pragma unroll
            for (int hrow = 0; hrow < 2; ++hrow) {
                int rr = r + hrow * 8;
                float v0 = fmaf(gm, a[hrow * 2 + 0], xb[(size_t)rr * N_ + n0 + c]);
                float v1 = fmaf(gm, a[hrow * 2 + 1], xb[(size_t)rr * N_ + n0 + c + 1]);
                *reinterpret_cast<u32*>(oH + (size_t)rr * N_ + n0 + c) =
                    packh2(__float2half_rn(v0), __float2half_rn(v1));
            }
        }
    }
}

// ---------------- adj: A-resident, 2 n-tiles per CTA (R13 form) ---------------
// smem: A chunks resident at 0,16K,32K,48K; B double buffer at 64K, 80K.
__global__ void __launch_bounds__(256, 2) k_adj_tc(const float* __restrict__ b_adj) {
    extern __shared__ __align__(1024) char sm[];
    u32 sb = smem_u32(sm);
    int tid = threadIdx.x, wid = tid >> 5, lane = tid & 31;
    int wm = (wid >> 1) * 32, wn = (wid & 1) * 64;
    int n0base = blockIdx.x * 256, m0 = blockIdx.y * 128, b = blockIdx.z;
    const f16* aH = g_wadjH + (size_t)m0 * K2C;
    const f16* bH = g_xcH + (size_t)b * K2C * N_ + n0base;

#pragma unroll
    for (int c = 0; c < 4; ++c) stA(sb + c * 16384, aH + c * 64, K2C, tid);
    stB(sb + 65536, bH, N_, tid);
    CP_COMMIT();
    stB(sb + 81920, bH + (size_t)64 * N_, N_, tid);
    CP_COMMIT();

    f16* oH = g_adjH + (size_t)b * N_ * N_;
#pragma unroll 1
    for (int nt = 0; nt < 2; ++nt) {
        float acc[2][8][4] = {};
#pragma unroll 1
        for (int kc = 0; kc < 4; ++kc) {
            int t = nt * 4 + kc;
            if (t + 1 < 8) CP_WAIT1(); else CP_WAIT0();
            __syncthreads();
            chunk_sp(sb + kc * 16384, sb + 65536 + (t & 1) * 16384, wm, wn,
                     lane, acc);
            __syncthreads();
            if (t + 2 < 8) {
                int t2 = t + 2;
                stB(sb + 65536 + (t & 1) * 16384,
                    bH + (size_t)(t2 & 3) * 64 * N_ + (t2 >> 2) * 128, N_, tid);
                CP_COMMIT();
            }
        }
        int n0 = n0base + nt * 128;
#pragma unroll
        for (int mf = 0; mf < 2; ++mf) {
            int r = wm + mf * 16 + (lane >> 2);
#pragma unroll
            for (int nf = 0; nf < 8; ++nf) {
                int c = wn + nf * 8 + (lane & 3) * 2;
                const float* a = acc[mf][nf];
#pragma unroll
                for (int hrow = 0; hrow < 2; ++hrow) {
                    int rr = r + hrow * 8;
                    float bias = b_adj[m0 + rr];
                    *reinterpret_cast<u32*>(oH + (size_t)(m0 + rr) * N_ + n0 + c) =
                        sigm2(a[hrow * 2 + 0] + bias, a[hrow * 2 + 1] + bias);
                }
            }
        }
    }
}

// ---------------- fused y1+y2: out = leaky(w_dyn @ leaky(x @ adj) + b) --------
__global__ void __launch_bounds__(256, 2) k_y1y2_tc(const float* __restrict__ b_dyn,
                                                    float* __restrict__ out) {
    extern __shared__ __align__(1024) char sm[];
    u32 sb = smem_u32(sm);
    int tid = threadIdx.x, wid = tid >> 5, lane = tid & 31;
    int wm = (wid >> 1) * 32, wn = (wid & 1) * 64;
    int n0 = blockIdx.x * 128, b = blockIdx.y;
    const f16* aH = g_xcH + ((size_t)b * K2C + 128) * N_;  // x rows, k contig
    const f16* bH = g_adjH + (size_t)b * N_ * N_ + n0;

    // --- y1 mainloop: acc = x @ adj tile ---
    float acc[2][8][4] = {};
    gemm_sp3(sb, aH, N_, bH, N_, 32, tid, wm, wn, lane, acc);
    __syncthreads();  // all warps done with all buffers before reuse

    // --- write leaky(y1) into smem B-layout: 64k-chunks at 0 and 16384 ---
#pragma unroll
    for (int mf = 0; mf < 2; ++mf) {
        int r = wm + mf * 16 + (lane >> 2);
#pragma unroll
        for (int nf = 0; nf < 8; ++nf) {
            int c = wn + nf * 8 + (lane & 3) * 2;
            const float* a = acc[mf][nf];
#pragma unroll
            for (int hrow = 0; hrow < 2; ++hrow) {
                int rr = r + hrow * 8;
                u32 v = packh2(__float2half_rn(leaky(a[hrow * 2 + 0])),
                               __float2half_rn(leaky(a[hrow * 2 + 1])));
                int kr = rr & 63, ch = c >> 3;
                u32 addr = sb + (rr >> 6) * 16384 + kr * 256 +
                           ((ch ^ (kr & 15)) & 15) * 16 + (c & 7) * 2;
                asm volatile("st.shared.b32 [%0], %1;" :: "r"(addr), "r"(v));
            }
        }
    }
    // stage w_dyn as A (2 chunks) into buffer 1 region
    stA(sb + 32768, g_wdynH, C_, tid);
    stA(sb + 49152, g_wdynH + 64, C_, tid);
    CP_COMMIT();
    CP_WAIT0();
    __syncthreads();

    // --- y2: acc2 = w_dyn @ y1_tile ---
    float acc2[2][8][4] = {};
    chunk_sp(sb + 32768, sb + 0, wm, wn, lane, acc2);
    chunk_sp(sb + 49152, sb + 16384, wm, wn, lane, acc2);

    float* ob = out + (size_t)b * C_ * N_;
#pragma unroll
    for (int mf = 0; mf < 2; ++mf) {
        int r = wm + mf * 16 + (lane >> 2);
#pragma unroll
        for (int nf = 0; nf < 8; ++nf) {
            int c = wn + nf * 8 + (lane & 3) * 2;
            const float* a = acc2[mf][nf];
#pragma unroll
            for (int hrow = 0; hrow < 2; ++hrow) {
                int rr = r + hrow * 8;
                float bias = b_dyn[rr];
                *reinterpret_cast<float2*>(ob + (size_t)rr * N_ + n0 + c) =
                    make_float2(leaky(a[hrow * 2 + 0] + bias),
                                leaky(a[hrow * 2 + 1] + bias));
            }
        }
    }
}

// ---------------- launch ----------------
extern "C" void kernel_launch(void* const* d_in, const int* in_sizes, int n_in,
                              void* d_out, int out_size) {
    const float* x     = (const float*)d_in[0];  // [8,128,2048]
    const float* w_adj = (const float*)d_in[1];  // [2048,256]
    const float* b_adj = (const float*)d_in[2];  // [2048]
    const float* w_dyn = (const float*)d_in[3];  // [128,128]
    const float* b_dyn = (const float*)d_in[4];  // [128]
    const float* gamma = (const float*)d_in[5];  // [1]
    float* out = (float*)d_out;                  // [8,128,2048]

    cudaFuncSetAttribute(k_energy_tc, cudaFuncAttributeMaxDynamicSharedMemorySize, SMEM_SZ);
    cudaFuncSetAttribute(k_xglb_tc, cudaFuncAttributeMaxDynamicSharedMemorySize, SMEM_SZ3);
    cudaFuncSetAttribute(k_adj_tc, cudaFuncAttributeMaxDynamicSharedMemorySize, SMEM_SZ3);
    cudaFuncSetAttribute(k_y1y2_tc, cudaFuncAttributeMaxDynamicSharedMemorySize, SMEM_SZ3);

    k_cvt<<<1024, 256>>>(w_adj, w_dyn, x);
    k_energy_tc<<<dim3(KSPLIT, B_), 256, SMEM_SZ>>>();
    k_softmax<<<256, 128>>>();
    k_xglb_tc<<<dim3(N_ / 128, B_), 256, SMEM_SZ3>>>(x, gamma);
    k_adj_tc<<<dim3(N_ / 256, N_ / 128, B_), 256, SMEM_SZ3>>>(b_adj);
    k_y1y2_tc<<<dim3(N_ / 128, B_), 256, SMEM_SZ3>>>(b_dyn, out);
}